// round 1
// baseline (speedup 1.0000x reference)
#include <cuda_runtime.h>
#include <math_constants.h>

// Problem constants (fixed by the dataset)
#define Bc 2
#define Hc 12
#define Nc 2048
#define Dc 128
#define Wc 64

// One warp per (b, h, n) query position.
// Lane L owns q[d] for d in [4L, 4L+4)  (32 lanes x float4 = 128).
// Per w: gather K row + V row (coalesced float4 per lane = one 128B line/lane),
// dot via butterfly reduce, online softmax update in registers.
__global__ void __launch_bounds__(256, 8) sparse_attn_kernel(
    const float* __restrict__ q,
    const float* __restrict__ k,
    const float* __restrict__ v,
    const int*   __restrict__ col_ids,
    float*       __restrict__ out)
{
    const int gwarp = (blockIdx.x * blockDim.x + threadIdx.x) >> 5;
    if (gwarp >= Bc * Hc * Nc) return;
    const int lane = threadIdx.x & 31;

    const int n  = gwarp & (Nc - 1);   // fast index: consecutive warps share bh slice
    const int bh = gwarp >> 11;        // Nc = 2048 = 2^11

    // q row for this query
    const float4* q4 = reinterpret_cast<const float4*>(q) + (size_t)gwarp * (Dc / 4);
    const float4 qv = q4[lane];

    // 64 column ids for this n: 2 per lane, broadcast later via shfl
    const int* cid = col_ids + n * Wc;
    const int c_lo = cid[lane];
    const int c_hi = cid[lane + 32];

    const float4* kb = reinterpret_cast<const float4*>(k) + (size_t)bh * Nc * (Dc / 4);
    const float4* vb = reinterpret_cast<const float4*>(v) + (size_t)bh * Nc * (Dc / 4);

    const float scale = 0.08838834764831845f;  // 1/sqrt(128)

    float  m = -CUDART_INF_F;
    float  l = 0.0f;
    float4 acc = make_float4(0.f, 0.f, 0.f, 0.f);

    #pragma unroll 4
    for (int w = 0; w < Wc; ++w) {
        // broadcast column id for this w (register shuffle, no memory op)
        const int c = __shfl_sync(0xffffffffu, (w < 32) ? c_lo : c_hi, w & 31);

        // gather K and V rows (independent of the softmax dep-chain -> MLP)
        const float4 kv = kb[(size_t)c * (Dc / 4) + lane];
        const float4 vv = vb[(size_t)c * (Dc / 4) + lane];

        // partial dot (4 elems per lane)
        float p = kv.x * qv.x + kv.y * qv.y + kv.z * qv.z + kv.w * qv.w;

        // butterfly reduce -> full dot in every lane
        p += __shfl_xor_sync(0xffffffffu, p, 16);
        p += __shfl_xor_sync(0xffffffffu, p, 8);
        p += __shfl_xor_sync(0xffffffffu, p, 4);
        p += __shfl_xor_sync(0xffffffffu, p, 2);
        p += __shfl_xor_sync(0xffffffffu, p, 1);

        const float s = p * scale;

        // online softmax update (warp-uniform values, no divergence)
        const float mn   = fmaxf(m, s);
        const float corr = __expf(m - mn);   // exp(-inf) = 0 handles first iter
        const float e    = __expf(s - mn);
        l = l * corr + e;
        acc.x = acc.x * corr + e * vv.x;
        acc.y = acc.y * corr + e * vv.y;
        acc.z = acc.z * corr + e * vv.z;
        acc.w = acc.w * corr + e * vv.w;
        m = mn;
    }

    const float inv = 1.0f / l;
    float4 o;
    o.x = acc.x * inv;
    o.y = acc.y * inv;
    o.z = acc.z * inv;
    o.w = acc.w * inv;
    reinterpret_cast<float4*>(out)[(size_t)gwarp * (Dc / 4) + lane] = o;
}

extern "C" void kernel_launch(void* const* d_in, const int* in_sizes, int n_in,
                              void* d_out, int out_size)
{
    const float* q   = (const float*)d_in[0];
    const float* k   = (const float*)d_in[1];
    const float* v   = (const float*)d_in[2];
    const int*   cid = (const int*)d_in[3];
    float*       out = (float*)d_out;

    const int total_warps = Bc * Hc * Nc;          // 49152
    const int threads     = 256;                   // 8 warps / block
    const int blocks      = (total_warps * 32 + threads - 1) / threads;  // 6144

    sparse_attn_kernel<<<blocks, threads>>>(q, k, v, cid, out);
}

// round 2
// speedup vs baseline: 1.4328x; 1.4328x over previous
#include <cuda_runtime.h>
#include <cuda_fp16.h>
#include <math_constants.h>

#define Bc 2
#define Hc 12
#define Nc 2048
#define Dc 128
#define Wc 64
#define TOT_ELEM (Bc*Hc*Nc*Dc)   // 6,291,456

// fp16-staged K and V (12.6 MB each) — device-global scratch, no allocation.
static __device__ __align__(16) __half g_kh[TOT_ELEM];
static __device__ __align__(16) __half g_vh[TOT_ELEM];

// ---------------------------------------------------------------------------
// Pre-pass: convert K and V fp32 -> fp16. Each thread converts 8 elements.
// ---------------------------------------------------------------------------
__global__ void __launch_bounds__(256) convert_fp16_kernel(
    const float4* __restrict__ k4, const float4* __restrict__ v4)
{
    const int n8 = TOT_ELEM / 8;             // 786,432 per tensor
    int i = blockIdx.x * blockDim.x + threadIdx.x;
    if (i >= 2 * n8) return;

    const float4* src;
    uint4* dst;
    if (i < n8) { src = k4; dst = reinterpret_cast<uint4*>(g_kh); }
    else        { src = v4; dst = reinterpret_cast<uint4*>(g_vh); i -= n8; }

    const float4 a = src[2 * i];
    const float4 b = src[2 * i + 1];
    __half2 h0 = __floats2half2_rn(a.x, a.y);
    __half2 h1 = __floats2half2_rn(a.z, a.w);
    __half2 h2 = __floats2half2_rn(b.x, b.y);
    __half2 h3 = __floats2half2_rn(b.z, b.w);
    uint4 o;
    o.x = *reinterpret_cast<unsigned*>(&h0);
    o.y = *reinterpret_cast<unsigned*>(&h1);
    o.z = *reinterpret_cast<unsigned*>(&h2);
    o.w = *reinterpret_cast<unsigned*>(&h3);
    dst[i] = o;
}

// Fold-merge: combine two per-lane partial-sum sets across xor `mask`.
// Lanes with `bit` clear end up carrying value-a reduced over the lane pair,
// lanes with `bit` set carry value-b.
__device__ __forceinline__ float fold(float a, float b, int mask, bool bit)
{
    float send = bit ? a : b;
    float keep = bit ? b : a;
    float recv = __shfl_xor_sync(0xffffffffu, send, mask);
    return keep + recv;
}

// ---------------------------------------------------------------------------
// Main: one warp per (b,h,n). Two-pass exact softmax.
//   Pass 1: 64 gathered K-row dots, fold-tree reduced (9 shfl / 8 dots).
//           Lane i holds score for j(i) = bit4 | bit3<<1 | bit2<<2 of lane id.
//   Softmax: exps distributed across lanes, butterfly over masks {4,8,16}.
//   Pass 2: broadcast normalized weights, gather V rows, accumulate.
// ---------------------------------------------------------------------------
__global__ void __launch_bounds__(256, 4) sparse_attn_kernel(
    const float* __restrict__ q,
    const int*   __restrict__ col_ids,
    float*       __restrict__ out)
{
    const unsigned FULL = 0xffffffffu;
    const int gwarp = (blockIdx.x * blockDim.x + threadIdx.x) >> 5;
    if (gwarp >= Bc * Hc * Nc) return;
    const int lane = threadIdx.x & 31;

    const int n  = gwarp & (Nc - 1);
    const int bh = gwarp >> 11;

    // q row, pre-scaled by 1/sqrt(D)
    const float scale = 0.08838834764831845f;
    float4 qv = reinterpret_cast<const float4*>(q)[(size_t)gwarp * (Dc / 4) + lane];
    qv.x *= scale; qv.y *= scale; qv.z *= scale; qv.w *= scale;

    // 64 column ids: 2 per lane, broadcast via shfl
    const int* cid = col_ids + n * Wc;
    const int c_lo = cid[lane];
    const int c_hi = cid[lane + 32];

    // fp16 K/V bases for this (b,h): rows of 128 halves = 32 uint2 each
    const uint2* kb = reinterpret_cast<const uint2*>(g_kh) + (size_t)bh * Nc * (Dc / 4);
    const uint2* vb = reinterpret_cast<const uint2*>(g_vh) + (size_t)bh * Nc * (Dc / 4);

    const bool b16 = (lane & 16) != 0;
    const bool b8  = (lane & 8)  != 0;
    const bool b4  = (lane & 4)  != 0;

    float sc[8];

    // ---- Pass 1: scores -----------------------------------------------
    #pragma unroll
    for (int g = 0; g < 8; ++g) {
        float p[8];
        #pragma unroll
        for (int j = 0; j < 8; ++j) {
            const int w = g * 8 + j;
            const int c = __shfl_sync(FULL, (w < 32) ? c_lo : c_hi, w & 31);
            const uint2 raw = kb[(size_t)c * (Dc / 4) + lane];
            const float2 f0 = __half22float2(*reinterpret_cast<const __half2*>(&raw.x));
            const float2 f1 = __half22float2(*reinterpret_cast<const __half2*>(&raw.y));
            p[j] = f0.x * qv.x + f0.y * qv.y + f1.x * qv.z + f1.y * qv.w;
        }
        // fold tree: 7 folds + 2 butterfly -> every lane of each 4-lane
        // group holds the full dot for its j(lane)
        float m0 = fold(p[0], p[1], 16, b16);
        float m1 = fold(p[2], p[3], 16, b16);
        float m2 = fold(p[4], p[5], 16, b16);
        float m3 = fold(p[6], p[7], 16, b16);
        float n0 = fold(m0, m1, 8, b8);
        float n1 = fold(m2, m3, 8, b8);
        float s  = fold(n0, n1, 4, b4);
        s += __shfl_xor_sync(FULL, s, 2);
        s += __shfl_xor_sync(FULL, s, 1);
        sc[g] = s;
    }

    // ---- Softmax (exact, distributed) ---------------------------------
    float mx = sc[0];
    #pragma unroll
    for (int g = 1; g < 8; ++g) mx = fmaxf(mx, sc[g]);
    mx = fmaxf(mx, __shfl_xor_sync(FULL, mx, 4));
    mx = fmaxf(mx, __shfl_xor_sync(FULL, mx, 8));
    mx = fmaxf(mx, __shfl_xor_sync(FULL, mx, 16));

    float e[8];
    float l = 0.0f;
    #pragma unroll
    for (int g = 0; g < 8; ++g) { e[g] = __expf(sc[g] - mx); l += e[g]; }
    l += __shfl_xor_sync(FULL, l, 4);
    l += __shfl_xor_sync(FULL, l, 8);
    l += __shfl_xor_sync(FULL, l, 16);

    const float inv = 1.0f / l;
    #pragma unroll
    for (int g = 0; g < 8; ++g) e[g] *= inv;

    // ---- Pass 2: weighted V gather ------------------------------------
    float4 acc = make_float4(0.f, 0.f, 0.f, 0.f);
    #pragma unroll
    for (int g = 0; g < 8; ++g) {
        #pragma unroll
        for (int j = 0; j < 8; ++j) {
            const int w = g * 8 + j;
            // lane holding w's weight: bits0..2 of j -> lane bits 4,3,2
            const int src = ((j & 1) << 4) | ((j & 2) << 2) | (j & 4);
            const float ew = __shfl_sync(FULL, e[g], src);
            const int c = __shfl_sync(FULL, (w < 32) ? c_lo : c_hi, w & 31);
            const uint2 raw = vb[(size_t)c * (Dc / 4) + lane];
            const float2 f0 = __half22float2(*reinterpret_cast<const __half2*>(&raw.x));
            const float2 f1 = __half22float2(*reinterpret_cast<const __half2*>(&raw.y));
            acc.x = fmaf(ew, f0.x, acc.x);
            acc.y = fmaf(ew, f0.y, acc.y);
            acc.z = fmaf(ew, f1.x, acc.z);
            acc.w = fmaf(ew, f1.y, acc.w);
        }
    }

    reinterpret_cast<float4*>(out)[(size_t)gwarp * (Dc / 4) + lane] = acc;
}

extern "C" void kernel_launch(void* const* d_in, const int* in_sizes, int n_in,
                              void* d_out, int out_size)
{
    const float* q   = (const float*)d_in[0];
    const float* k   = (const float*)d_in[1];
    const float* v   = (const float*)d_in[2];
    const int*   cid = (const int*)d_in[3];
    float*       out = (float*)d_out;

    // Pre-pass: fp32 -> fp16 staging of K and V
    {
        const int threads = 256;
        const int work    = 2 * (TOT_ELEM / 8);
        const int blocks  = (work + threads - 1) / threads;
        convert_fp16_kernel<<<blocks, threads>>>(
            reinterpret_cast<const float4*>(k),
            reinterpret_cast<const float4*>(v));
    }

    // Main kernel: one warp per query
    {
        const int total_warps = Bc * Hc * Nc;   // 49152
        const int threads     = 256;
        const int blocks      = (total_warps * 32 + threads - 1) / threads;
        sparse_attn_kernel<<<blocks, threads>>>(q, cid, out);
    }
}

// round 3
// speedup vs baseline: 1.8040x; 1.2590x over previous
#include <cuda_runtime.h>
#include <cuda_fp16.h>
#include <math_constants.h>

#define Bc 2
#define Hc 12
#define Nc 2048
#define Dc 128
#define Wc 64
#define TOT_ELEM (Bc*Hc*Nc*Dc)   // 6,291,456

// fp16-staged K and V — device-global scratch (no allocation).
static __device__ __align__(16) __half g_kh[TOT_ELEM];
static __device__ __align__(16) __half g_vh[TOT_ELEM];

// ---------------------------------------------------------------------------
// Pre-pass: convert K and V fp32 -> fp16 (8 elems / thread).
// ---------------------------------------------------------------------------
__global__ void __launch_bounds__(256) convert_fp16_kernel(
    const float4* __restrict__ k4, const float4* __restrict__ v4)
{
    const int n8 = TOT_ELEM / 8;
    int i = blockIdx.x * blockDim.x + threadIdx.x;
    if (i >= 2 * n8) return;

    const float4* src;
    uint4* dst;
    if (i < n8) { src = k4; dst = reinterpret_cast<uint4*>(g_kh); }
    else        { src = v4; dst = reinterpret_cast<uint4*>(g_vh); i -= n8; }

    const float4 a = src[2 * i];
    const float4 b = src[2 * i + 1];
    __half2 h0 = __floats2half2_rn(a.x, a.y);
    __half2 h1 = __floats2half2_rn(a.z, a.w);
    __half2 h2 = __floats2half2_rn(b.x, b.y);
    __half2 h3 = __floats2half2_rn(b.z, b.w);
    uint4 o;
    o.x = *reinterpret_cast<unsigned*>(&h0);
    o.y = *reinterpret_cast<unsigned*>(&h1);
    o.z = *reinterpret_cast<unsigned*>(&h2);
    o.w = *reinterpret_cast<unsigned*>(&h3);
    dst[i] = o;
}

// Fold-merge across xor `mask`: lanes with `bit` clear end up with a-pair-sum,
// lanes with `bit` set with b-pair-sum. 2 SEL + SHFL + FADD in SASS.
__device__ __forceinline__ float fold(float a, float b, int mask, bool bit)
{
    float send = bit ? a : b;
    float keep = bit ? b : a;
    float recv = __shfl_xor_sync(0xffffffffu, send, mask);
    return keep + recv;
}

// ---------------------------------------------------------------------------
// Main: one warp per (b,h,n). Dual-row layout:
//   each LDG.128 fetches TWO gathered rows (lanes 0-15 -> row 2j, 16-31 -> 2j+1),
//   lane covers 8 consecutive d-elements of its row.
// Pass 1: scores via 2-deep HFMA2 partials + fold tree per 16-row group.
// Softmax: exact, scores distributed across lanes (dup on bit0 only).
// Pass 2: dual-row V gather, fp32 FFMA accumulate, halves merged via xor-16.
// ---------------------------------------------------------------------------
__global__ void __launch_bounds__(256, 4) sparse_attn_kernel(
    const float* __restrict__ q,
    const int*   __restrict__ col_ids,
    float*       __restrict__ out)
{
    const unsigned FULL = 0xffffffffu;
    const int gwarp = (blockIdx.x * blockDim.x + threadIdx.x) >> 5;
    if (gwarp >= Bc * Hc * Nc) return;
    const int lane    = threadIdx.x & 31;
    const int lanelow = lane & 15;          // position within 16-lane half
    const int halfsel = lane >> 4;          // 0 or 1

    const int n  = gwarp & (Nc - 1);
    const int bh = gwarp >> 11;

    // q for this lane's 8 d-elements, pre-scaled by 1/sqrt(D), stored as half2.
    const float scale = 0.08838834764831845f;
    const float4* q4 = reinterpret_cast<const float4*>(q) + (size_t)gwarp * (Dc / 4);
    const float4 qa = q4[lanelow * 2];
    const float4 qb = q4[lanelow * 2 + 1];
    __half2 qh[4];
    qh[0] = __floats2half2_rn(qa.x * scale, qa.y * scale);
    qh[1] = __floats2half2_rn(qa.z * scale, qa.w * scale);
    qh[2] = __floats2half2_rn(qb.x * scale, qb.y * scale);
    qh[3] = __floats2half2_rn(qb.z * scale, qb.w * scale);

    // 64 column ids: 2 per lane
    const int* cid = col_ids + n * Wc;
    const int c_lo = cid[lane];
    const int c_hi = cid[lane + 32];

    // K/V bases for this bh (row = 16 uint4)
    const uint4* kb4 = reinterpret_cast<const uint4*>(g_kh) + (size_t)bh * Nc * 16;
    const uint4* vb4 = reinterpret_cast<const uint4*>(g_vh) + (size_t)bh * Nc * 16;

    const bool bit8 = (lane & 8) != 0;
    const bool bit4 = (lane & 4) != 0;
    const bool bit2 = (lane & 2) != 0;

    // ---- Pass 1: scores ------------------------------------------------
    // Group g covers rows [g*16, g*16+16). Step j loads rows (g*16+2j, +1).
    // After folding, lane L holds the score of row g*16 + 2*jL + bit4(L),
    // jL = b3 + 2*b2 + 4*b1, duplicated across bit0.
    float sc[4];
    #pragma unroll
    for (int g = 0; g < 4; ++g) {
        float p[8];
        #pragma unroll
        for (int j = 0; j < 8; ++j) {
            const int w0  = g * 16 + 2 * j;
            const int src = (w0 & 31) + halfsel;
            const int c   = __shfl_sync(FULL, (g < 2) ? c_lo : c_hi, src);
            const uint4 raw = kb4[c * 16 + lanelow];
            const __half2 h0 = *reinterpret_cast<const __half2*>(&raw.x);
            const __half2 h1 = *reinterpret_cast<const __half2*>(&raw.y);
            const __half2 h2 = *reinterpret_cast<const __half2*>(&raw.z);
            const __half2 h3 = *reinterpret_cast<const __half2*>(&raw.w);
            __half2 a2 = __hmul2(h0, qh[0]);
            a2 = __hfma2(h1, qh[1], a2);
            __half2 b2 = __hmul2(h2, qh[2]);
            b2 = __hfma2(h3, qh[3], b2);
            const float2 fa = __half22float2(a2);
            const float2 fb = __half22float2(b2);
            p[j] = (fa.x + fa.y) + (fb.x + fb.y);
        }
        float q0 = fold(p[0], p[1], 8, bit8);
        float q1 = fold(p[2], p[3], 8, bit8);
        float q2 = fold(p[4], p[5], 8, bit8);
        float q3 = fold(p[6], p[7], 8, bit8);
        float r0 = fold(q0, q1, 4, bit4);
        float r1 = fold(q2, q3, 4, bit4);
        float s  = fold(r0, r1, 2, bit2);
        s += __shfl_xor_sync(FULL, s, 1);
        sc[g] = s;
    }

    // ---- Softmax (exact, distributed over lane bits 1..4) --------------
    float mx = fmaxf(fmaxf(sc[0], sc[1]), fmaxf(sc[2], sc[3]));
    mx = fmaxf(mx, __shfl_xor_sync(FULL, mx, 2));
    mx = fmaxf(mx, __shfl_xor_sync(FULL, mx, 4));
    mx = fmaxf(mx, __shfl_xor_sync(FULL, mx, 8));
    mx = fmaxf(mx, __shfl_xor_sync(FULL, mx, 16));

    float e[4];
    e[0] = __expf(sc[0] - mx);
    e[1] = __expf(sc[1] - mx);
    e[2] = __expf(sc[2] - mx);
    e[3] = __expf(sc[3] - mx);
    float l = (e[0] + e[1]) + (e[2] + e[3]);
    l += __shfl_xor_sync(FULL, l, 2);
    l += __shfl_xor_sync(FULL, l, 4);
    l += __shfl_xor_sync(FULL, l, 8);
    l += __shfl_xor_sync(FULL, l, 16);

    const float inv = 1.0f / l;
    e[0] *= inv; e[1] *= inv; e[2] *= inv; e[3] *= inv;

    // ---- Pass 2: weighted V gather -------------------------------------
    float acc[8];
    #pragma unroll
    for (int i = 0; i < 8; ++i) acc[i] = 0.0f;

    const int lane16 = lane & 16;
    #pragma unroll
    for (int g = 0; g < 4; ++g) {
        #pragma unroll
        for (int j = 0; j < 8; ++j) {
            const int w0   = g * 16 + 2 * j;
            const int srcc = (w0 & 31) + halfsel;
            const int c    = __shfl_sync(FULL, (g < 2) ? c_lo : c_hi, srcc);
            // lane holding row (2j + half)'s weight: bits (b3,b2,b1) = j bits, b4 = half
            const int srcw = ((j & 1) << 3) | ((j & 2) << 1) | ((j & 4) >> 1) | lane16;
            const float ew = __shfl_sync(FULL, e[g], srcw);
            const uint4 raw = vb4[c * 16 + lanelow];
            const float2 f0 = __half22float2(*reinterpret_cast<const __half2*>(&raw.x));
            const float2 f1 = __half22float2(*reinterpret_cast<const __half2*>(&raw.y));
            const float2 f2 = __half22float2(*reinterpret_cast<const __half2*>(&raw.z));
            const float2 f3 = __half22float2(*reinterpret_cast<const __half2*>(&raw.w));
            acc[0] = fmaf(ew, f0.x, acc[0]);
            acc[1] = fmaf(ew, f0.y, acc[1]);
            acc[2] = fmaf(ew, f1.x, acc[2]);
            acc[3] = fmaf(ew, f1.y, acc[3]);
            acc[4] = fmaf(ew, f2.x, acc[4]);
            acc[5] = fmaf(ew, f2.y, acc[5]);
            acc[6] = fmaf(ew, f3.x, acc[6]);
            acc[7] = fmaf(ew, f3.y, acc[7]);
        }
    }

    // merge the two 16-lane halves (even rows + odd rows)
    #pragma unroll
    for (int i = 0; i < 8; ++i)
        acc[i] += __shfl_xor_sync(FULL, acc[i], 16);

    if (lane < 16) {
        float4* o4 = reinterpret_cast<float4*>(out) + (size_t)gwarp * (Dc / 4);
        float4 oa, ob;
        oa.x = acc[0]; oa.y = acc[1]; oa.z = acc[2]; oa.w = acc[3];
        ob.x = acc[4]; ob.y = acc[5]; ob.z = acc[6]; ob.w = acc[7];
        o4[lanelow * 2]     = oa;
        o4[lanelow * 2 + 1] = ob;
    }
}

extern "C" void kernel_launch(void* const* d_in, const int* in_sizes, int n_in,
                              void* d_out, int out_size)
{
    const float* q   = (const float*)d_in[0];
    const float* k   = (const float*)d_in[1];
    const float* v   = (const float*)d_in[2];
    const int*   cid = (const int*)d_in[3];
    float*       out = (float*)d_out;

    {
        const int threads = 256;
        const int work    = 2 * (TOT_ELEM / 8);
        const int blocks  = (work + threads - 1) / threads;
        convert_fp16_kernel<<<blocks, threads>>>(
            reinterpret_cast<const float4*>(k),
            reinterpret_cast<const float4*>(v));
    }
    {
        const int total_warps = Bc * Hc * Nc;
        const int threads     = 256;
        const int blocks      = (total_warps * 32 + threads - 1) / threads;
        sparse_attn_kernel<<<blocks, threads>>>(q, cid, out);
    }
}

// round 4
// speedup vs baseline: 1.8074x; 1.0019x over previous
#include <cuda_runtime.h>
#include <cuda_fp16.h>
#include <math_constants.h>

#define Bc 2
#define Hc 12
#define Nc 2048
#define Dc 128
#define Wc 64
#define TOT_ELEM (Bc*Hc*Nc*Dc)   // 6,291,456

// fp16-staged K and V — device-global scratch (no allocation).
static __device__ __align__(16) __half g_kh[TOT_ELEM];
static __device__ __align__(16) __half g_vh[TOT_ELEM];

// ---------------------------------------------------------------------------
// Pre-pass: convert K and V fp32 -> fp16 (8 elems / thread).
// ---------------------------------------------------------------------------
__global__ void __launch_bounds__(256) convert_fp16_kernel(
    const float4* __restrict__ k4, const float4* __restrict__ v4)
{
    const int n8 = TOT_ELEM / 8;
    int i = blockIdx.x * blockDim.x + threadIdx.x;
    if (i >= 2 * n8) return;

    const float4* src;
    uint4* dst;
    if (i < n8) { src = k4; dst = reinterpret_cast<uint4*>(g_kh); }
    else        { src = v4; dst = reinterpret_cast<uint4*>(g_vh); i -= n8; }

    const float4 a = src[2 * i];
    const float4 b = src[2 * i + 1];
    __half2 h0 = __floats2half2_rn(a.x, a.y);
    __half2 h1 = __floats2half2_rn(a.z, a.w);
    __half2 h2 = __floats2half2_rn(b.x, b.y);
    __half2 h3 = __floats2half2_rn(b.z, b.w);
    uint4 o;
    o.x = *reinterpret_cast<unsigned*>(&h0);
    o.y = *reinterpret_cast<unsigned*>(&h1);
    o.z = *reinterpret_cast<unsigned*>(&h2);
    o.w = *reinterpret_cast<unsigned*>(&h3);
    dst[i] = o;
}

// Fold-merge across xor `mask`: lanes with `bit` clear end up with a-pair-sum,
// lanes with `bit` set with b-pair-sum. 2 SEL + SHFL + FADD in SASS.
__device__ __forceinline__ float fold(float a, float b, int mask, bool bit)
{
    float send = bit ? a : b;
    float keep = bit ? b : a;
    float recv = __shfl_xor_sync(0xffffffffu, send, mask);
    return keep + recv;
}

// ---------------------------------------------------------------------------
// Main: one warp per (b,h,n). Dual-row layout:
//   each LDG.128 fetches TWO gathered rows (lanes 0-15 -> row 2j, 16-31 -> 2j+1),
//   lane covers 8 consecutive d-elements of its row.
// Pass 1: scores via 2-deep HFMA2 partials + fold tree per 16-row group.
// Softmax: exact, scores distributed across lanes (dup on bit0 only).
// Pass 2: dual-row V gather, fp32 FFMA accumulate, halves merged via xor-16.
// ---------------------------------------------------------------------------
__global__ void __launch_bounds__(256, 4) sparse_attn_kernel(
    const float* __restrict__ q,
    const int*   __restrict__ col_ids,
    float*       __restrict__ out)
{
    const unsigned FULL = 0xffffffffu;
    const int gwarp = (blockIdx.x * blockDim.x + threadIdx.x) >> 5;
    if (gwarp >= Bc * Hc * Nc) return;
    const int lane    = threadIdx.x & 31;
    const int lanelow = lane & 15;          // position within 16-lane half
    const int halfsel = lane >> 4;          // 0 or 1

    const int n  = gwarp & (Nc - 1);
    const int bh = gwarp >> 11;

    // q for this lane's 8 d-elements, pre-scaled by 1/sqrt(D), stored as half2.
    const float scale = 0.08838834764831845f;
    const float4* q4 = reinterpret_cast<const float4*>(q) + (size_t)gwarp * (Dc / 4);
    const float4 qa = q4[lanelow * 2];
    const float4 qb = q4[lanelow * 2 + 1];
    __half2 qh[4];
    qh[0] = __floats2half2_rn(qa.x * scale, qa.y * scale);
    qh[1] = __floats2half2_rn(qa.z * scale, qa.w * scale);
    qh[2] = __floats2half2_rn(qb.x * scale, qb.y * scale);
    qh[3] = __floats2half2_rn(qb.z * scale, qb.w * scale);

    // 64 column ids: 2 per lane
    const int* cid = col_ids + n * Wc;
    const int c_lo = cid[lane];
    const int c_hi = cid[lane + 32];

    // K/V bases for this bh (row = 16 uint4)
    const uint4* kb4 = reinterpret_cast<const uint4*>(g_kh) + (size_t)bh * Nc * 16;
    const uint4* vb4 = reinterpret_cast<const uint4*>(g_vh) + (size_t)bh * Nc * 16;

    const bool bit8 = (lane & 8) != 0;
    const bool bit4 = (lane & 4) != 0;
    const bool bit2 = (lane & 2) != 0;

    // ---- Pass 1: scores ------------------------------------------------
    // Group g covers rows [g*16, g*16+16). Step j loads rows (g*16+2j, +1).
    // After folding, lane L holds the score of row g*16 + 2*jL + bit4(L),
    // jL = b3 + 2*b2 + 4*b1, duplicated across bit0.
    float sc[4];
    #pragma unroll
    for (int g = 0; g < 4; ++g) {
        float p[8];
        #pragma unroll
        for (int j = 0; j < 8; ++j) {
            const int w0  = g * 16 + 2 * j;
            const int src = (w0 & 31) + halfsel;
            const int c   = __shfl_sync(FULL, (g < 2) ? c_lo : c_hi, src);
            const uint4 raw = kb4[c * 16 + lanelow];
            const __half2 h0 = *reinterpret_cast<const __half2*>(&raw.x);
            const __half2 h1 = *reinterpret_cast<const __half2*>(&raw.y);
            const __half2 h2 = *reinterpret_cast<const __half2*>(&raw.z);
            const __half2 h3 = *reinterpret_cast<const __half2*>(&raw.w);
            __half2 a2 = __hmul2(h0, qh[0]);
            a2 = __hfma2(h1, qh[1], a2);
            __half2 b2 = __hmul2(h2, qh[2]);
            b2 = __hfma2(h3, qh[3], b2);
            const float2 fa = __half22float2(a2);
            const float2 fb = __half22float2(b2);
            p[j] = (fa.x + fa.y) + (fb.x + fb.y);
        }
        float q0 = fold(p[0], p[1], 8, bit8);
        float q1 = fold(p[2], p[3], 8, bit8);
        float q2 = fold(p[4], p[5], 8, bit8);
        float q3 = fold(p[6], p[7], 8, bit8);
        float r0 = fold(q0, q1, 4, bit4);
        float r1 = fold(q2, q3, 4, bit4);
        float s  = fold(r0, r1, 2, bit2);
        s += __shfl_xor_sync(FULL, s, 1);
        sc[g] = s;
    }

    // ---- Softmax (exact, distributed over lane bits 1..4) --------------
    float mx = fmaxf(fmaxf(sc[0], sc[1]), fmaxf(sc[2], sc[3]));
    mx = fmaxf(mx, __shfl_xor_sync(FULL, mx, 2));
    mx = fmaxf(mx, __shfl_xor_sync(FULL, mx, 4));
    mx = fmaxf(mx, __shfl_xor_sync(FULL, mx, 8));
    mx = fmaxf(mx, __shfl_xor_sync(FULL, mx, 16));

    float e[4];
    e[0] = __expf(sc[0] - mx);
    e[1] = __expf(sc[1] - mx);
    e[2] = __expf(sc[2] - mx);
    e[3] = __expf(sc[3] - mx);
    float l = (e[0] + e[1]) + (e[2] + e[3]);
    l += __shfl_xor_sync(FULL, l, 2);
    l += __shfl_xor_sync(FULL, l, 4);
    l += __shfl_xor_sync(FULL, l, 8);
    l += __shfl_xor_sync(FULL, l, 16);

    const float inv = 1.0f / l;
    e[0] *= inv; e[1] *= inv; e[2] *= inv; e[3] *= inv;

    // ---- Pass 2: weighted V gather -------------------------------------
    float acc[8];
    #pragma unroll
    for (int i = 0; i < 8; ++i) acc[i] = 0.0f;

    const int lane16 = lane & 16;
    #pragma unroll
    for (int g = 0; g < 4; ++g) {
        #pragma unroll
        for (int j = 0; j < 8; ++j) {
            const int w0   = g * 16 + 2 * j;
            const int srcc = (w0 & 31) + halfsel;
            const int c    = __shfl_sync(FULL, (g < 2) ? c_lo : c_hi, srcc);
            // lane holding row (2j + half)'s weight: bits (b3,b2,b1) = j bits, b4 = half
            const int srcw = ((j & 1) << 3) | ((j & 2) << 1) | ((j & 4) >> 1) | lane16;
            const float ew = __shfl_sync(FULL, e[g], srcw);
            const uint4 raw = vb4[c * 16 + lanelow];
            const float2 f0 = __half22float2(*reinterpret_cast<const __half2*>(&raw.x));
            const float2 f1 = __half22float2(*reinterpret_cast<const __half2*>(&raw.y));
            const float2 f2 = __half22float2(*reinterpret_cast<const __half2*>(&raw.z));
            const float2 f3 = __half22float2(*reinterpret_cast<const __half2*>(&raw.w));
            acc[0] = fmaf(ew, f0.x, acc[0]);
            acc[1] = fmaf(ew, f0.y, acc[1]);
            acc[2] = fmaf(ew, f1.x, acc[2]);
            acc[3] = fmaf(ew, f1.y, acc[3]);
            acc[4] = fmaf(ew, f2.x, acc[4]);
            acc[5] = fmaf(ew, f2.y, acc[5]);
            acc[6] = fmaf(ew, f3.x, acc[6]);
            acc[7] = fmaf(ew, f3.y, acc[7]);
        }
    }

    // merge the two 16-lane halves (even rows + odd rows)
    #pragma unroll
    for (int i = 0; i < 8; ++i)
        acc[i] += __shfl_xor_sync(FULL, acc[i], 16);

    if (lane < 16) {
        float4* o4 = reinterpret_cast<float4*>(out) + (size_t)gwarp * (Dc / 4);
        float4 oa, ob;
        oa.x = acc[0]; oa.y = acc[1]; oa.z = acc[2]; oa.w = acc[3];
        ob.x = acc[4]; ob.y = acc[5]; ob.z = acc[6]; ob.w = acc[7];
        o4[lanelow * 2]     = oa;
        o4[lanelow * 2 + 1] = ob;
    }
}

extern "C" void kernel_launch(void* const* d_in, const int* in_sizes, int n_in,
                              void* d_out, int out_size)
{
    const float* q   = (const float*)d_in[0];
    const float* k   = (const float*)d_in[1];
    const float* v   = (const float*)d_in[2];
    const int*   cid = (const int*)d_in[3];
    float*       out = (float*)d_out;

    {
        const int threads = 256;
        const int work    = 2 * (TOT_ELEM / 8);
        const int blocks  = (work + threads - 1) / threads;
        convert_fp16_kernel<<<blocks, threads>>>(
            reinterpret_cast<const float4*>(k),
            reinterpret_cast<const float4*>(v));
    }
    {
        const int total_warps = Bc * Hc * Nc;
        const int threads     = 256;
        const int blocks      = (total_warps * 32 + threads - 1) / threads;
        sparse_attn_kernel<<<blocks, threads>>>(q, cid, out);
    }
}